// round 9
// baseline (speedup 1.0000x reference)
#include <cuda_runtime.h>
#include <cstdint>

// NATTEN 1D attention, fp32, TF32 tensor cores, banded per-warp windows.
// B=2, L=2048, D=512, H=8, hd=64, K=63.
// CTA: 128 queries, 8 warps (16 queries each). W slab [200 x 64] staged
// pre-rounded tf32. GEMM1 ks-outer/j-inner: 26 batched independent LDS then
// 11 mma on independent accumulators (no RAW chains), single B buffer
// (low reg pressure). Epilogue exp2+mask -> P (tf32-rounded). GEMM2
// j-outer/nt-inner, small double buffer. Normalize, store.

#define BB 2
#define LL 2048
#define HH 8
#define HD 64
#define DD 512
#define KK 63
#define HALF 31
#define QTILE 128
#define THREADS 256
#define WROWS 200              // max band reach: warp7 nt0=14 -> rows < 200
#define WPITCH 68              // % 32 == 4 -> conflict-free fragment loads
#define PP 100                 // % 32 == 4 -> conflict-free GEMM2 A (P) loads
#define NT 11                  // band tiles of 8 cols
#define SCALE2 0.1803368801f   // 64^-0.5 * log2(e); exp == exp2f

#define SM_W (WROWS * WPITCH)          // 13600 floats
#define SM_P (8 * 16 * PP)             // 12800 floats
#define SMEM_BYTES ((SM_W + SM_P) * 4) // 105600 B -> 2 CTAs/SM

__device__ __forceinline__ uint32_t tf32_rna(float x) {
    uint32_t r;
    asm("cvt.rna.tf32.f32 %0, %1;" : "=r"(r) : "f"(x));
    return r;
}
__device__ __forceinline__ float tf32f(float x) {
    return __uint_as_float(tf32_rna(x));
}

__device__ __forceinline__ void mma_tf32(float c[4], const uint32_t a[4], const uint32_t b[2]) {
    asm("mma.sync.aligned.m16n8k8.row.col.f32.tf32.tf32.f32 "
        "{%0,%1,%2,%3}, {%4,%5,%6,%7}, {%8,%9}, {%0,%1,%2,%3};"
        : "+f"(c[0]), "+f"(c[1]), "+f"(c[2]), "+f"(c[3])
        : "r"(a[0]), "r"(a[1]), "r"(a[2]), "r"(a[3]),
          "r"(b[0]), "r"(b[1]));
}

__global__ __launch_bounds__(THREADS, 2)
void natten1d_tc(const float* __restrict__ x, float* __restrict__ out) {
    extern __shared__ float smem[];
    float* W = smem;                 // [WROWS][WPITCH], tf32-rounded
    float* P = smem + SM_W;          // 8 warps x [16][PP]

    const int tile = blockIdx.x;
    const int h    = blockIdx.y;
    const int b    = blockIdx.z;
    const int tid  = threadIdx.x;
    const int lane = tid & 31;
    const int warp = tid >> 5;

    const int base   = tile * QTILE;
    const int origin = base - HALF;

    // ---- Stage W rows [origin, origin+200) clipped to [0,L), tf32-rounded ----
    const float* xb = x + ((size_t)b * LL) * DD + h * HD;
    for (int i = tid; i < WROWS * 16; i += THREADS) {
        int r = i >> 4;
        int c = i & 15;
        int g = origin + r;
        float4 v = make_float4(0.f, 0.f, 0.f, 0.f);
        if ((unsigned)g < (unsigned)LL)
            v = *(const float4*)(xb + (size_t)g * DD + c * 4);
        v.x = tf32f(v.x); v.y = tf32f(v.y); v.z = tf32f(v.z); v.w = tf32f(v.w);
        *(float4*)(W + r * WPITCH + c * 4) = v;
    }
    __syncthreads();

    const int g = lane >> 2;   // 0..7
    const int t = lane & 3;    // 0..3
    const int q0 = warp * 16;

    int stf = base + q0 - HALF;
    if (stf < 0) stf = 0;
    if (stf > LL - KK) stf = LL - KK;
    const int nt0 = (stf - origin) >> 3;

    const int p0 = base + q0 + g;
    const int p1 = p0 + 8;
    int s0c = p0 - HALF; if (s0c < 0) s0c = 0; if (s0c > LL - KK) s0c = LL - KK;
    int s1c = p1 - HALF; if (s1c < 0) s1c = 0; if (s1c > LL - KK) s1c = LL - KK;
    const int o0 = s0c - origin;
    const int o1 = s1c - origin;

    const float* qr0 = W + (q0 + g + HALF) * WPITCH;   // row of query p0
    const float* qr1 = qr0 + 8 * WPITCH;               // row of query p1
    const float* wband = W + (nt0 * 8 + g) * WPITCH + t;  // GEMM1 B base

    // ================= GEMM1: ks-outer, j-inner (no acc chains) =========
    float sacc[NT][4];
    #pragma unroll
    for (int j = 0; j < NT; j++)
        #pragma unroll
        for (int i = 0; i < 4; i++) sacc[j][i] = 0.f;

    #pragma unroll
    for (int ks = 0; ks < 8; ks++) {
        // A fragment for this ks (prescaled)
        uint32_t a[4];
        a[0] = __float_as_uint(qr0[ks * 8 + t] * SCALE2);
        a[1] = __float_as_uint(qr1[ks * 8 + t] * SCALE2);
        a[2] = __float_as_uint(qr0[ks * 8 + t + 4] * SCALE2);
        a[3] = __float_as_uint(qr1[ks * 8 + t + 4] * SCALE2);
        // B fragments for all 11 band tiles at this ks: 22 independent,
        // conflict-free LDS.
        uint32_t bb[22];
        {
            const float* p = wband + ks * 8;
            #pragma unroll
            for (int j = 0; j < NT; j++) {
                bb[2 * j]     = __float_as_uint(p[0]);
                bb[2 * j + 1] = __float_as_uint(p[4]);
                p += 8 * WPITCH;
            }
        }
        // 11 mma on 11 distinct accumulators: back-to-back issue, no RAW.
        #pragma unroll
        for (int j = 0; j < NT; j++)
            mma_tf32(sacc[j], a, &bb[2 * j]);
    }

    // ================= Epilogue: P = tf32(exp2(S))*mask -> smem ==========
    float sum0 = 0.f, sum1 = 0.f;
    float* Pr0 = P + (warp * 16 + g) * PP;
    float* Pr1 = Pr0 + 8 * PP;
    #pragma unroll
    for (int j = 0; j < NT; j++) {
        int j0 = (nt0 + j) * 8 + 2 * t;
        int j1 = j0 + 1;
        float e00 = ((unsigned)(j0 - o0) < (unsigned)KK) ? tf32f(exp2f(sacc[j][0])) : 0.f;
        float e01 = ((unsigned)(j1 - o0) < (unsigned)KK) ? tf32f(exp2f(sacc[j][1])) : 0.f;
        float e10 = ((unsigned)(j0 - o1) < (unsigned)KK) ? tf32f(exp2f(sacc[j][2])) : 0.f;
        float e11 = ((unsigned)(j1 - o1) < (unsigned)KK) ? tf32f(exp2f(sacc[j][3])) : 0.f;
        sum0 += e00 + e01;
        sum1 += e10 + e11;
        int bc = j * 8 + 2 * t;
        *(float2*)(Pr0 + bc) = make_float2(e00, e01);
        *(float2*)(Pr1 + bc) = make_float2(e10, e11);
    }
    __syncwarp();   // P written by quad-mates, read cross-lane below

    // ================= GEMM2: j-outer, nt-inner (independent accs) =======
    float oacc[8][4];
    #pragma unroll
    for (int nt = 0; nt < 8; nt++)
        #pragma unroll
        for (int i = 0; i < 4; i++) oacc[nt][i] = 0.f;

    uint32_t PA[2][4], WB[2][16];
    // prologue loads for j = 0
    PA[0][0] = __float_as_uint(Pr0[t]);
    PA[0][1] = __float_as_uint(Pr1[t]);
    PA[0][2] = __float_as_uint(Pr0[t + 4]);
    PA[0][3] = __float_as_uint(Pr1[t + 4]);
    {
        const float* p = W + (nt0 * 8 + t) * WPITCH + g;
        #pragma unroll
        for (int nt = 0; nt < 8; nt++) {
            WB[0][2 * nt]     = __float_as_uint(p[nt * 8]);
            WB[0][2 * nt + 1] = __float_as_uint(p[4 * WPITCH + nt * 8]);
        }
    }
    #pragma unroll
    for (int j = 0; j < NT; j++) {
        if (j + 1 < NT) {
            int nx = (j + 1) & 1;
            PA[nx][0] = __float_as_uint(Pr0[(j + 1) * 8 + t]);
            PA[nx][1] = __float_as_uint(Pr1[(j + 1) * 8 + t]);
            PA[nx][2] = __float_as_uint(Pr0[(j + 1) * 8 + t + 4]);
            PA[nx][3] = __float_as_uint(Pr1[(j + 1) * 8 + t + 4]);
            const float* p = W + ((nt0 + j + 1) * 8 + t) * WPITCH + g;
            #pragma unroll
            for (int nt = 0; nt < 8; nt++) {
                WB[nx][2 * nt]     = __float_as_uint(p[nt * 8]);
                WB[nx][2 * nt + 1] = __float_as_uint(p[4 * WPITCH + nt * 8]);
            }
        }
        uint32_t* pa = PA[j & 1];
        uint32_t* wb = WB[j & 1];
        #pragma unroll
        for (int nt = 0; nt < 8; nt++)
            mma_tf32(oacc[nt], pa, &wb[2 * nt]);
    }

    // ---- Denominators (deferred reduction) ----
    sum0 += __shfl_xor_sync(0xffffffffu, sum0, 1);
    sum0 += __shfl_xor_sync(0xffffffffu, sum0, 2);
    sum1 += __shfl_xor_sync(0xffffffffu, sum1, 1);
    sum1 += __shfl_xor_sync(0xffffffffu, sum1, 2);
    const float inv0 = 1.0f / sum0;
    const float inv1 = 1.0f / sum1;

    // ================= Normalize + store =================
    float* orow0 = out + ((size_t)(b * LL + p0)) * DD + h * HD;
    float* orow1 = out + ((size_t)(b * LL + p1)) * DD + h * HD;
    #pragma unroll
    for (int nt = 0; nt < 8; nt++) {
        int d0 = nt * 8 + 2 * t;
        *(float2*)(orow0 + d0) = make_float2(oacc[nt][0] * inv0, oacc[nt][1] * inv0);
        *(float2*)(orow1 + d0) = make_float2(oacc[nt][2] * inv1, oacc[nt][3] * inv1);
    }
}

extern "C" void kernel_launch(void* const* d_in, const int* in_sizes, int n_in,
                              void* d_out, int out_size) {
    (void)in_sizes; (void)n_in; (void)out_size;
    const float* x = (const float*)d_in[0];
    float* out = (float*)d_out;

    cudaFuncSetAttribute(natten1d_tc,
                         cudaFuncAttributeMaxDynamicSharedMemorySize, SMEM_BYTES);

    dim3 grid(LL / QTILE, HH, BB);   // 16 x 8 x 2 = 256 CTAs
    natten1d_tc<<<grid, THREADS, SMEM_BYTES>>>(x, out);
}

// round 11
// speedup vs baseline: 1.0385x; 1.0385x over previous
#include <cuda_runtime.h>
#include <cstdint>

// NATTEN 1D attention, fp32, TF32 tensor cores, warp-PAIR split per 16-query
// group. B=2, L=2048, D=512, H=8, hd=64, K=63.
// CTA: 128 queries, 512 threads (16 warps). Warp pair (qgroup, role):
//   role 0: GEMM1 band tiles 0..5,  GEMM2 output cols  0..31
//   role 1: GEMM1 band tiles 6..10, GEMM2 output cols 32..63
// P and partial row-sums shared via smem; CTA-wide __syncthreads between
// phases (uniform control flow).

#define BB 2
#define LL 2048
#define HH 8
#define HD 64
#define DD 512
#define KK 63
#define HALF 31
#define QTILE 128
#define THREADS 512
#define WROWS 200
#define WPITCH 68              // % 32 == 4 -> conflict-free GEMM1 B loads
#define PP 100                 // % 32 == 4 -> conflict-free GEMM2 A (P) loads
#define NT 11
#define SCALE2 0.1803368801f   // 64^-0.5 * log2(e)

#define SM_W (WROWS * WPITCH)           // 13600 floats
#define SM_P (8 * 16 * PP)              // 12800 floats
#define SM_R 256                        // rsum[8 qgroups][2 roles][16 rows]
#define SMEM_BYTES ((SM_W + SM_P + SM_R) * 4)   // 106624 B -> 2 CTAs/SM

__device__ __forceinline__ uint32_t tf32_rna(float x) {
    uint32_t r;
    asm("cvt.rna.tf32.f32 %0, %1;" : "=r"(r) : "f"(x));
    return r;
}
__device__ __forceinline__ float tf32f(float x) {
    return __uint_as_float(tf32_rna(x));
}

__device__ __forceinline__ void mma_tf32(float c[4], const uint32_t a[4], const uint32_t b[2]) {
    asm("mma.sync.aligned.m16n8k8.row.col.f32.tf32.tf32.f32 "
        "{%0,%1,%2,%3}, {%4,%5,%6,%7}, {%8,%9}, {%0,%1,%2,%3};"
        : "+f"(c[0]), "+f"(c[1]), "+f"(c[2]), "+f"(c[3])
        : "r"(a[0]), "r"(a[1]), "r"(a[2]), "r"(a[3]),
          "r"(b[0]), "r"(b[1]));
}

// GEMM1 over NTJ band tiles: ks-outer, j-inner (independent accumulators).
template <int NTJ>
__device__ __forceinline__ void gemm1_band(float (*sacc)[4],
                                           const float* qr0, const float* qr1,
                                           const float* wband, int t) {
    #pragma unroll
    for (int ks = 0; ks < 8; ks++) {
        uint32_t a[4];
        a[0] = __float_as_uint(qr0[ks * 8 + t] * SCALE2);
        a[1] = __float_as_uint(qr1[ks * 8 + t] * SCALE2);
        a[2] = __float_as_uint(qr0[ks * 8 + t + 4] * SCALE2);
        a[3] = __float_as_uint(qr1[ks * 8 + t + 4] * SCALE2);
        uint32_t bb[2 * NTJ];
        const float* p = wband + ks * 8;
        #pragma unroll
        for (int j = 0; j < NTJ; j++) {
            bb[2 * j]     = __float_as_uint(p[0]);
            bb[2 * j + 1] = __float_as_uint(p[4]);
            p += 8 * WPITCH;
        }
        #pragma unroll
        for (int j = 0; j < NTJ; j++)
            mma_tf32(sacc[j], a, &bb[2 * j]);
    }
}

// Epilogue over NTJ tiles: e = tf32(exp2(s)) masked; write P; accumulate sums.
template <int NTJ>
__device__ __forceinline__ void epilogue_band(float (*sacc)[4],
                                              float* Pr0, float* Pr1,
                                              int colbase, int pcol,
                                              int o0, int o1,
                                              float& sum0, float& sum1, int t) {
    #pragma unroll
    for (int j = 0; j < NTJ; j++) {
        int j0 = colbase + j * 8 + 2 * t;
        int j1 = j0 + 1;
        float e00 = ((unsigned)(j0 - o0) < (unsigned)KK) ? tf32f(exp2f(sacc[j][0])) : 0.f;
        float e01 = ((unsigned)(j1 - o0) < (unsigned)KK) ? tf32f(exp2f(sacc[j][1])) : 0.f;
        float e10 = ((unsigned)(j0 - o1) < (unsigned)KK) ? tf32f(exp2f(sacc[j][2])) : 0.f;
        float e11 = ((unsigned)(j1 - o1) < (unsigned)KK) ? tf32f(exp2f(sacc[j][3])) : 0.f;
        sum0 += e00 + e01;
        sum1 += e10 + e11;
        int bc = pcol + j * 8 + 2 * t;
        *(float2*)(Pr0 + bc) = make_float2(e00, e01);
        *(float2*)(Pr1 + bc) = make_float2(e10, e11);
    }
}

__global__ __launch_bounds__(THREADS, 2)
void natten1d_tc(const float* __restrict__ x, float* __restrict__ out) {
    extern __shared__ float smem[];
    float* W  = smem;                      // [WROWS][WPITCH], tf32-rounded
    float* P  = smem + SM_W;               // 8 qgroups x [16][PP]
    float* RS = smem + SM_W + SM_P;        // [8][2][16] partial row sums

    const int tile = blockIdx.x;
    const int h    = blockIdx.y;
    const int b    = blockIdx.z;
    const int tid  = threadIdx.x;
    const int lane = tid & 31;
    const int warp = tid >> 5;             // 0..15
    const int qg   = warp >> 1;            // 0..7 query group
    const int role = warp & 1;             // 0: tiles 0-5 / cols 0-31; 1: tiles 6-10 / cols 32-63

    const int base   = tile * QTILE;
    const int origin = base - HALF;

    // ---- Stage W rows [origin, origin+200) clipped to [0,L), tf32-rounded ----
    const float* xb = x + ((size_t)b * LL) * DD + h * HD;
    for (int i = tid; i < WROWS * 16; i += THREADS) {
        int r = i >> 4;
        int c = i & 15;
        int g = origin + r;
        float4 v = make_float4(0.f, 0.f, 0.f, 0.f);
        if ((unsigned)g < (unsigned)LL)
            v = *(const float4*)(xb + (size_t)g * DD + c * 4);
        v.x = tf32f(v.x); v.y = tf32f(v.y); v.z = tf32f(v.z); v.w = tf32f(v.w);
        *(float4*)(W + r * WPITCH + c * 4) = v;
    }
    __syncthreads();

    const int g = lane >> 2;   // 0..7
    const int t = lane & 3;    // 0..3
    const int q0 = qg * 16;

    int stf = base + q0 - HALF;
    if (stf < 0) stf = 0;
    if (stf > LL - KK) stf = LL - KK;
    const int nt0 = (stf - origin) >> 3;

    const int p0 = base + q0 + g;
    const int p1 = p0 + 8;
    int s0c = p0 - HALF; if (s0c < 0) s0c = 0; if (s0c > LL - KK) s0c = LL - KK;
    int s1c = p1 - HALF; if (s1c < 0) s1c = 0; if (s1c > LL - KK) s1c = LL - KK;
    const int o0 = s0c - origin;
    const int o1 = s1c - origin;

    const float* qr0 = W + (q0 + g + HALF) * WPITCH;
    const float* qr1 = qr0 + 8 * WPITCH;

    const int jbase = role ? 6 : 0;                      // first band tile
    const float* wband = W + ((nt0 + jbase) * 8 + g) * WPITCH + t;

    float* Pr0 = P + (qg * 16 + g) * PP;
    float* Pr1 = Pr0 + 8 * PP;
    const int colbase = (nt0 + jbase) * 8;               // global col of first tile
    const int pcol    = jbase * 8;                       // P-local col of first tile

    // ========== GEMM1 + epilogue on this warp's band half ==========
    float sacc[6][4];
    #pragma unroll
    for (int j = 0; j < 6; j++)
        #pragma unroll
        for (int i = 0; i < 4; i++) sacc[j][i] = 0.f;

    float sum0 = 0.f, sum1 = 0.f;
    if (role == 0) {
        gemm1_band<6>(sacc, qr0, qr1, wband, t);
        epilogue_band<6>(sacc, Pr0, Pr1, colbase, pcol, o0, o1, sum0, sum1, t);
    } else {
        gemm1_band<5>(sacc, qr0, qr1, wband, t);
        epilogue_band<5>(sacc, Pr0, Pr1, colbase, pcol, o0, o1, sum0, sum1, t);
    }

    // quad reduce partial sums (cols split across t)
    sum0 += __shfl_xor_sync(0xffffffffu, sum0, 1);
    sum0 += __shfl_xor_sync(0xffffffffu, sum0, 2);
    sum1 += __shfl_xor_sync(0xffffffffu, sum1, 1);
    sum1 += __shfl_xor_sync(0xffffffffu, sum1, 2);
    if (t == 0) {
        RS[qg * 32 + role * 16 + g]     = sum0;
        RS[qg * 32 + role * 16 + g + 8] = sum1;
    }

    // CTA barrier: P halves + partial sums visible across every warp pair.
    // (Uniform control flow: all 512 threads reach this point.)
    __syncthreads();

    const float inv0 = 1.0f / (RS[qg * 32 + g]     + RS[qg * 32 + 16 + g]);
    const float inv1 = 1.0f / (RS[qg * 32 + g + 8] + RS[qg * 32 + 16 + g + 8]);

    // ========== GEMM2: O[16 x 32] (this role's column half) ==========
    float oacc[4][4];
    #pragma unroll
    for (int nt = 0; nt < 4; nt++)
        #pragma unroll
        for (int i = 0; i < 4; i++) oacc[nt][i] = 0.f;

    const int ncol = role * 32;                          // output col offset
    #pragma unroll
    for (int j = 0; j < NT; j++) {
        uint32_t pa[4];
        pa[0] = __float_as_uint(Pr0[j * 8 + t]);
        pa[1] = __float_as_uint(Pr1[j * 8 + t]);
        pa[2] = __float_as_uint(Pr0[j * 8 + t + 4]);
        pa[3] = __float_as_uint(Pr1[j * 8 + t + 4]);
        const float* wr = W + ((nt0 + j) * 8 + t) * WPITCH + ncol + g;
        uint32_t wb[8];
        #pragma unroll
        for (int nt = 0; nt < 4; nt++) {
            wb[2 * nt]     = __float_as_uint(wr[nt * 8]);
            wb[2 * nt + 1] = __float_as_uint(wr[4 * WPITCH + nt * 8]);
        }
        #pragma unroll
        for (int nt = 0; nt < 4; nt++)
            mma_tf32(oacc[nt], pa, &wb[2 * nt]);
    }

    // ========== Normalize + store ==========
    float* orow0 = out + ((size_t)(b * LL + p0)) * DD + h * HD + ncol;
    float* orow1 = out + ((size_t)(b * LL + p1)) * DD + h * HD + ncol;
    #pragma unroll
    for (int nt = 0; nt < 4; nt++) {
        int d0 = nt * 8 + 2 * t;
        *(float2*)(orow0 + d0) = make_float2(oacc[nt][0] * inv0, oacc[nt][1] * inv0);
        *(float2*)(orow1 + d0) = make_float2(oacc[nt][2] * inv1, oacc[nt][3] * inv1);
    }
}

extern "C" void kernel_launch(void* const* d_in, const int* in_sizes, int n_in,
                              void* d_out, int out_size) {
    (void)in_sizes; (void)n_in; (void)out_size;
    const float* x = (const float*)d_in[0];
    float* out = (float*)d_out;

    cudaFuncSetAttribute(natten1d_tc,
                         cudaFuncAttributeMaxDynamicSharedMemorySize, SMEM_BYTES);

    dim3 grid(LL / QTILE, HH, BB);   // 16 x 8 x 2 = 256 CTAs
    natten1d_tc<<<grid, THREADS, SMEM_BYTES>>>(x, out);
}